// round 17
// baseline (speedup 1.0000x reference)
#include <cuda_runtime.h>
#include <cuda_bf16.h>
#include <mma.h>
#include <math.h>
#include <stdint.h>

using namespace nvcuda;

#define NT 4096      // tokens
#define DM 1024      // d_model
#define NH 4096      // hidden
#define NE 8         // experts
#define NSLOTS (NT * 2)

#define TM 128       // CTA tile M
#define TN 64        // CTA tile N
#define KCH 16       // K per chunk (one wmma k-step)
#define LDA 24       // A smem stride (bf16): 48B rows, conflict-free LDSM
#define LDB 72       // B smem stride (bf16): 144B rows, conflict-free LDSM
#define LDC 64       // C smem stride (fp32)

// -------- device scratch: same 134 MB total as proven R2/R13 --------
__device__ float g_combine[NT * NE];
__device__ int   g_list[NE * NT];
__device__ int   g_count[NE];
__device__ int   g_offset[NE + 1];
__device__ __align__(16) __nv_bfloat16 g_hb_hi[(size_t)NSLOTS * NH];  // 67 MB
__device__ __align__(16) __nv_bfloat16 g_hb_lo[(size_t)NSLOTS * NH];  // 67 MB

// ----------------- helpers -----------------
__device__ __forceinline__ void split2(float x, float y, uint32_t& hi, uint32_t& lo) {
    __nv_bfloat16 hx = __float2bfloat16(x), hy = __float2bfloat16(y);
    __nv_bfloat162 h2 = __halves2bfloat162(hx, hy);
    __nv_bfloat162 l2 = __halves2bfloat162(
        __float2bfloat16(x - __bfloat162float(hx)),
        __float2bfloat16(y - __bfloat162float(hy)));
    hi = *(uint32_t*)&h2;
    lo = *(uint32_t*)&l2;
}
__device__ __forceinline__ void split8(const float4& a, const float4& b,
                                       uint4& hi, uint4& lo) {
    split2(a.x, a.y, hi.x, lo.x);
    split2(a.z, a.w, hi.y, lo.y);
    split2(b.x, b.y, hi.z, lo.z);
    split2(b.z, b.w, hi.w, lo.w);
}
__device__ __forceinline__ void split4(const float4& a, uint2& hi, uint2& lo) {
    split2(a.x, a.y, hi.x, lo.x);
    split2(a.z, a.w, hi.y, lo.y);
}

// ----------------- small kernels (proven) -----------------
__global__ void zero_kernel(float* __restrict__ out, int n) {
    int i = blockIdx.x * blockDim.x + threadIdx.x;
    if (i < n) out[i] = 0.0f;
    if (blockIdx.x == 0 && threadIdx.x < NE) g_count[threadIdx.x] = 0;
}

__global__ void router_kernel(const float* __restrict__ x,
                              const float* __restrict__ Wr) {
    int warp = (blockIdx.x * blockDim.x + threadIdx.x) >> 5;
    int lane = threadIdx.x & 31;
    if (warp >= NT) return;
    const float* xr = x + (size_t)warp * DM;
    float acc[NE];
#pragma unroll
    for (int e = 0; e < NE; e++) acc[e] = 0.0f;
    for (int d = lane; d < DM; d += 32) {
        float xv = xr[d];
        const float4* w4 = reinterpret_cast<const float4*>(Wr + (size_t)d * NE);
        float4 wa = w4[0], wb = w4[1];
        acc[0] = fmaf(xv, wa.x, acc[0]); acc[1] = fmaf(xv, wa.y, acc[1]);
        acc[2] = fmaf(xv, wa.z, acc[2]); acc[3] = fmaf(xv, wa.w, acc[3]);
        acc[4] = fmaf(xv, wb.x, acc[4]); acc[5] = fmaf(xv, wb.y, acc[5]);
        acc[6] = fmaf(xv, wb.z, acc[6]); acc[7] = fmaf(xv, wb.w, acc[7]);
    }
#pragma unroll
    for (int e = 0; e < NE; e++)
#pragma unroll
        for (int off = 16; off > 0; off >>= 1)
            acc[e] += __shfl_xor_sync(0xffffffffu, acc[e], off);
    if (lane == 0) {
        int e1 = 0;
#pragma unroll
        for (int e = 1; e < NE; e++) if (acc[e] > acc[e1]) e1 = e;
        int e2 = (e1 == 0) ? 1 : 0;
#pragma unroll
        for (int e = 0; e < NE; e++) {
            if (e == e1) continue;
            if (acc[e] > acc[e2]) e2 = e;
        }
        float w1 = 1.0f / (1.0f + expf(acc[e2] - acc[e1]));
        float w2 = 1.0f - w1;
        float* crow = g_combine + (size_t)warp * NE;
#pragma unroll
        for (int e = 0; e < NE; e++) crow[e] = 0.0f;
        crow[e1] = w1; crow[e2] = w2;
        int p1 = atomicAdd(&g_count[e1], 1);
        g_list[e1 * NT + p1] = warp;
        int p2 = atomicAdd(&g_count[e2], 1);
        g_list[e2 * NT + p2] = warp;
    }
}

__global__ void prefix_kernel() {
    if (threadIdx.x == 0) {
        int o = 0;
        for (int e = 0; e < NE; e++) { g_offset[e] = o; o += g_count[e]; }
        g_offset[NE] = o;
    }
}

// =========================================================================
// GEMM1: x @ {Wg,Wu}, double-buffered, in-register bf16 hi/lo split,
// 3-term compensated wmma, SiLU epilogue -> g_hb_hi/lo.
// Stage (21504 B): Ah 0(6144) | Al 6144 | BgH 12288(2304) | BgL 14592 |
//                  BuH 16896 | BuL 19200.   2 stages = 43008 B.
// =========================================================================
#define A_LO_B   6144
#define BG_HI_B  12288
#define BU_HI_B  16896
#define B_LO_D   2304       // hi->lo distance inside B block
#define STG1     21504
#define SMEM1    (2 * STG1)

__global__ void __launch_bounds__(256)
gemm1_kernel(const float* __restrict__ x,
             const float* __restrict__ Wg,
             const float* __restrict__ Wu) {
    extern __shared__ __align__(128) char smem[];
    int e = blockIdx.z;
    int cnt = g_count[e];
    int m0 = blockIdx.y * TM;
    if (m0 >= cnt) return;
    int n0 = blockIdx.x * TN;
    int base = g_offset[e];
    const int* list = g_list + e * NT;

    float* Cs = (float*)smem;
    int tid = threadIdx.x, wid = tid >> 5;
    int wr = wid >> 1, wc = wid & 1;     // warp grid 4m x 2n, warp tile 32x32

    // A: row = tid>>1 (0..127), 8 fp32 at (tid&1)*8
    int ar = tid >> 1, ah8 = (tid & 1) * 8;
    int arr = (m0 + ar < cnt) ? m0 + ar : m0;
    const float* aPtr = x + (size_t)list[arr] * DM + ah8;
    uint32_t aOff = (uint32_t)(ar * LDA + ah8) * 2;
    // B: tid<128 -> Wg, else Wu; k-row = (tid&127)>>3, 8 fp32 at ((tid&127)&7)*8
    int bsel = tid >> 7, bi = tid & 127;
    int bkr = bi >> 3, bnf = (bi & 7) * 8;
    const float* bPtr = (bsel ? Wu : Wg) + ((size_t)e * DM + bkr) * NH + n0 + bnf;
    uint32_t bOff = (bsel ? BU_HI_B : BG_HI_B) + (uint32_t)(bkr * LDB + bnf) * 2;

    wmma::fragment<wmma::accumulator, 16, 16, 16, float> accg[2][2], accu[2][2];
#pragma unroll
    for (int mi = 0; mi < 2; mi++)
#pragma unroll
        for (int ni = 0; ni < 2; ni++) {
            wmma::fill_fragment(accg[mi][ni], 0.0f);
            wmma::fill_fragment(accu[mi][ni], 0.0f);
        }

    const int NCH = DM / KCH;   // 64
    float4 la0, la1, lb0, lb1;

    auto load_regs = [&](int c) {
        int ko = c * KCH;
        la0 = *(const float4*)(aPtr + ko);
        la1 = *(const float4*)(aPtr + ko + 4);
        const float* bp = bPtr + (size_t)ko * NH;
        lb0 = *(const float4*)(bp);
        lb1 = *(const float4*)(bp + 4);
    };
    auto store_stage = [&](int s) {
        char* st = smem + s * STG1;
        uint4 h, l;
        split8(la0, la1, h, l);
        *(uint4*)(st + aOff)          = h;
        *(uint4*)(st + A_LO_B + aOff) = l;
        split8(lb0, lb1, h, l);
        *(uint4*)(st + bOff)          = h;
        *(uint4*)(st + bOff + B_LO_D) = l;
    };
    auto compute = [&](int s) {
        const char* st = smem + s * STG1;
        wmma::fragment<wmma::matrix_a, 16, 16, 16, __nv_bfloat16, wmma::row_major> ahf[2], alf[2];
#pragma unroll
        for (int mi = 0; mi < 2; mi++) {
            const __nv_bfloat16* ap = (const __nv_bfloat16*)st + (wr * 32 + mi * 16) * LDA;
            wmma::load_matrix_sync(ahf[mi], ap, LDA);
            wmma::load_matrix_sync(alf[mi], ap + A_LO_B / 2, LDA);
        }
        wmma::fragment<wmma::matrix_b, 16, 16, 16, __nv_bfloat16, wmma::row_major> bgh[2], bgl[2], buh[2], bul[2];
#pragma unroll
        for (int ni = 0; ni < 2; ni++) {
            uint32_t co = (uint32_t)(wc * 32 + ni * 16) * 2;
            wmma::load_matrix_sync(bgh[ni], (const __nv_bfloat16*)(st + BG_HI_B + co), LDB);
            wmma::load_matrix_sync(bgl[ni], (const __nv_bfloat16*)(st + BG_HI_B + B_LO_D + co), LDB);
            wmma::load_matrix_sync(buh[ni], (const __nv_bfloat16*)(st + BU_HI_B + co), LDB);
            wmma::load_matrix_sync(bul[ni], (const __nv_bfloat16*)(st + BU_HI_B + B_LO_D + co), LDB);
        }
#pragma unroll
        for (int mi = 0; mi < 2; mi++)
#pragma unroll
            for (int ni = 0; ni < 2; ni++) {
                wmma::mma_sync(accg[mi][ni], ahf[mi], bgh[ni], accg[mi][ni]);
                wmma::mma_sync(accg[mi][ni], ahf[mi], bgl[ni], accg[mi][ni]);
                wmma::mma_sync(accg[mi][ni], alf[mi], bgh[ni], accg[mi][ni]);
                wmma::mma_sync(accu[mi][ni], ahf[mi], buh[ni], accu[mi][ni]);
                wmma::mma_sync(accu[mi][ni], ahf[mi], bul[ni], accu[mi][ni]);
                wmma::mma_sync(accu[mi][ni], alf[mi], buh[ni], accu[mi][ni]);
            }
    };

    load_regs(0);
    store_stage(0);
    __syncthreads();
    for (int c = 0; c < NCH; c++) {
        int s = c & 1;
        if (c + 1 < NCH) load_regs(c + 1);
        compute(s);
        if (c + 1 < NCH) store_stage(s ^ 1);
        __syncthreads();
    }

    // ---- epilogue via smem C buffer (two passes) ----
    int r = tid >> 1, cb = (tid & 1) * 32;
#pragma unroll
    for (int mi = 0; mi < 2; mi++)
#pragma unroll
        for (int ni = 0; ni < 2; ni++)
            wmma::store_matrix_sync(Cs + (wr * 32 + mi * 16) * LDC + wc * 32 + ni * 16,
                                    accg[mi][ni], LDC, wmma::mem_row_major);
    __syncthreads();
    float gv[32];
#pragma unroll
    for (int j = 0; j < 32; j++) gv[j] = Cs[r * LDC + cb + j];
    __syncthreads();
#pragma unroll
    for (int mi = 0; mi < 2; mi++)
#pragma unroll
        for (int ni = 0; ni < 2; ni++)
            wmma::store_matrix_sync(Cs + (wr * 32 + mi * 16) * LDC + wc * 32 + ni * 16,
                                    accu[mi][ni], LDC, wmma::mem_row_major);
    __syncthreads();

    int mg = m0 + r;
    if (mg < cnt) {
        int tok = list[mg];
        float w = g_combine[(size_t)tok * NE + e];
        size_t rowb = (size_t)(base + mg) * NH + n0 + cb;
#pragma unroll
        for (int j = 0; j < 32; j += 2) {
            float g0 = gv[j], g1 = gv[j + 1];
            float u0 = Cs[r * LDC + cb + j], u1 = Cs[r * LDC + cb + j + 1];
            float h0 = g0 / (1.0f + __expf(-g0)) * u0 * w;
            float h1 = g1 / (1.0f + __expf(-g1)) * u1 * w;
            uint32_t hh, ll;
            split2(h0, h1, hh, ll);
            *(uint32_t*)(g_hb_hi + rowb + j) = hh;
            *(uint32_t*)(g_hb_lo + rowb + j) = ll;
        }
    }
}

// =========================================================================
// GEMM2: hbuf(bf16 hi/lo, direct copy) @ Wd(fp32 split), double-buffered,
// 3-term wmma, scatter-add epilogue.
// Stage (16896 B): Ah 0(6144) | Al 6144 | BH 12288(2304) | BL 14592.
// 2 stages = 33792 B.
// =========================================================================
#define B2_HI_B 12288
#define STG2    16896
#define SMEM2   (2 * STG2)

__global__ void __launch_bounds__(256)
gemm2_kernel(const float* __restrict__ Wd, float* __restrict__ out) {
    extern __shared__ __align__(128) char smem[];
    int e = blockIdx.z;
    int cnt = g_count[e];
    int m0 = blockIdx.y * TM;
    if (m0 >= cnt) return;
    int n0 = blockIdx.x * TN;
    int base = g_offset[e];
    const int* list = g_list + e * NT;

    float* Cs = (float*)smem;
    int tid = threadIdx.x, wid = tid >> 5;
    int wr = wid >> 1, wc = wid & 1;

    // A: bf16 hi/lo straight copy. row = tid>>1, 8 bf16 at (tid&1)*8
    int ar = tid >> 1, ah8 = (tid & 1) * 8;
    int arr = (m0 + ar < cnt) ? m0 + ar : m0;
    size_t aro = (size_t)(base + arr) * NH + ah8;
    const __nv_bfloat16* aHi = g_hb_hi + aro;
    const __nv_bfloat16* aLo = g_hb_lo + aro;
    uint32_t aOff = (uint32_t)(ar * LDA + ah8) * 2;
    // B: k-row = tid>>4 (0..15), 4 fp32 at (tid&15)*4
    int bkr = tid >> 4, bnf = (tid & 15) * 4;
    const float* bPtr = Wd + ((size_t)e * NH + bkr) * DM + n0 + bnf;
    uint32_t bOff = B2_HI_B + (uint32_t)(bkr * LDB + bnf) * 2;

    wmma::fragment<wmma::accumulator, 16, 16, 16, float> acc[2][2];
#pragma unroll
    for (int mi = 0; mi < 2; mi++)
#pragma unroll
        for (int ni = 0; ni < 2; ni++)
            wmma::fill_fragment(acc[mi][ni], 0.0f);

    const int NCH = NH / KCH;   // 256
    uint4 lah, lal;
    float4 lb;

    auto load_regs = [&](int c) {
        int ko = c * KCH;
        lah = *(const uint4*)(aHi + ko);
        lal = *(const uint4*)(aLo + ko);
        lb  = *(const float4*)(bPtr + (size_t)ko * DM);
    };
    auto store_stage = [&](int s) {
        char* st = smem + s * STG2;
        *(uint4*)(st + aOff)          = lah;
        *(uint4*)(st + A_LO_B + aOff) = lal;
        uint2 h, l;
        split4(lb, h, l);
        *(uint2*)(st + bOff)          = h;
        *(uint2*)(st + bOff + B_LO_D) = l;
    };
    auto compute = [&](int s) {
        const char* st = smem + s * STG2;
        wmma::fragment<wmma::matrix_a, 16, 16, 16, __nv_bfloat16, wmma::row_major> ahf[2], alf[2];
#pragma unroll
        for (int mi = 0; mi < 2; mi++) {
            const __nv_bfloat16* ap = (const __nv_bfloat16*)st + (wr * 32 + mi * 16) * LDA;
            wmma::load_matrix_sync(ahf[mi], ap, LDA);
            wmma::load_matrix_sync(alf[mi], ap + A_LO_B / 2, LDA);
        }
        wmma::fragment<wmma::matrix_b, 16, 16, 16, __nv_bfloat16, wmma::row_major> bh[2], bl[2];
#pragma unroll
        for (int ni = 0; ni < 2; ni++) {
            uint32_t co = (uint32_t)(wc * 32 + ni * 16) * 2;
            wmma::load_matrix_sync(bh[ni], (const __nv_bfloat16*)(st + B2_HI_B + co), LDB);
            wmma::load_matrix_sync(bl[ni], (const __nv_bfloat16*)(st + B2_HI_B + B_LO_D + co), LDB);
        }
#pragma unroll
        for (int mi = 0; mi < 2; mi++)
#pragma unroll
            for (int ni = 0; ni < 2; ni++) {
                wmma::mma_sync(acc[mi][ni], ahf[mi], bh[ni], acc[mi][ni]);
                wmma::mma_sync(acc[mi][ni], ahf[mi], bl[ni], acc[mi][ni]);
                wmma::mma_sync(acc[mi][ni], alf[mi], bh[ni], acc[mi][ni]);
            }
    };

    load_regs(0);
    store_stage(0);
    __syncthreads();
    for (int c = 0; c < NCH; c++) {
        int s = c & 1;
        if (c + 1 < NCH) load_regs(c + 1);
        compute(s);
        if (c + 1 < NCH) store_stage(s ^ 1);
        __syncthreads();
    }

    // epilogue: C buffer -> scatter-add
#pragma unroll
    for (int mi = 0; mi < 2; mi++)
#pragma unroll
        for (int ni = 0; ni < 2; ni++)
            wmma::store_matrix_sync(Cs + (wr * 32 + mi * 16) * LDC + wc * 32 + ni * 16,
                                    acc[mi][ni], LDC, wmma::mem_row_major);
    __syncthreads();

    int r = tid >> 1, cb = (tid & 1) * 32;
    int mg = m0 + r;
    if (mg < cnt) {
        int tok = list[mg];
        float* orow = out + (size_t)tok * DM + n0 + cb;
#pragma unroll
        for (int j = 0; j < 32; j++)
            atomicAdd(orow + j, Cs[r * LDC + cb + j]);
    }
}

// ----------------- launch -----------------
extern "C" void kernel_launch(void* const* d_in, const int* in_sizes, int n_in,
                              void* d_out, int out_size) {
    const float* x  = (const float*)d_in[0];
    const float* Wg = (const float*)d_in[1];
    const float* Wu = (const float*)d_in[2];
    const float* Wd = (const float*)d_in[3];
    const float* Wr = (const float*)d_in[4];
    float* out = (float*)d_out;

    zero_kernel<<<(out_size + 255) / 256, 256>>>(out, out_size);
    router_kernel<<<NT / 8, 256>>>(x, Wr);
    prefix_kernel<<<1, 32>>>();

    gemm1_kernel<<<dim3(NH / TN, NT / TM, NE), 256, SMEM1>>>(x, Wg, Wu);
    gemm2_kernel<<<dim3(DM / TN, NT / TM, NE), 256, SMEM2>>>(Wd, out);
}